// round 14
// baseline (speedup 1.0000x reference)
#include <cuda_runtime.h>
#include <cstdint>
#include <cstddef>
#include <math.h>

// ---------------------------------------------------------------------------
// LSTM  I=256 H=512 O=10 B=64 T=2048  (fp32, f32x2 packed-FMA pipe)
// R14: R13 (16.33ms) with the global-max barrier replaced by per-CTA flags
//      + per-chunk producer-group gating:
//   - chunk p of h is produced by CTAs [32p,32p+32); consumer warp p polls
//     those 32 flags (one coalesced 128B line) and issues that chunk's TMA
//     as soon as ITS producers are done -> straggler overlaps compute.
//   - GEMM phases still gate on per-chunk mbars (unchanged from R13).
//   - publish: per-CTA release store (no contended counter).
// ---------------------------------------------------------------------------

#define TSZ  2048
#define NCTA 128

typedef unsigned long long ull;

// scratch (__device__ globals are the sanctioned scratch mechanism)
__device__ float    g_xg[268435456];     // 1 GiB: [T][4H][B]  (2048*2048*64)
__device__ float    g_h[2 * 512 * 64];   // double-buffered h: [H][B]
__device__ float    g_bias[2048];        // b_ih + b_hh
__device__ unsigned g_flags[NCTA];       // per-CTA completed-step counters

// ---- packed f32x2 helpers (Blackwell dual-fp32 pipe) ----------------------
__device__ __forceinline__ ull splat2(float a) {
    ull r; asm("mov.b64 %0,{%1,%1};" : "=l"(r) : "f"(a)); return r;
}
__device__ __forceinline__ ull fma2(ull a, ull b, ull c) {
    ull d; asm("fma.rn.f32x2 %0,%1,%2,%3;" : "=l"(d) : "l"(a), "l"(b), "l"(c));
    return d;
}
__device__ __forceinline__ void upk2(ull v, float& a, float& b) {
    asm("mov.b64 {%0,%1},%2;" : "=f"(a), "=f"(b) : "l"(v));
}

// fast activations (rel err ~1e-6; budget 1e-3)
__device__ __forceinline__ float fsig(float x) {
    return __fdividef(1.0f, 1.0f + __expf(-x));
}
__device__ __forceinline__ float ftanh(float x) {
    return 1.0f - __fdividef(2.0f, __expf(2.0f * x) + 1.0f);
}

// ---- smem / mbarrier / bulk-copy helpers ----------------------------------
__device__ __forceinline__ uint32_t s2u(const void* p) {
    uint32_t a;
    asm("{ .reg .u64 t; cvta.to.shared.u64 t, %1; cvt.u32.u64 %0, t; }"
        : "=r"(a) : "l"(p));
    return a;
}
__device__ __forceinline__ void mbar_init(uint32_t m, unsigned cnt) {
    asm volatile("mbarrier.init.shared.b64 [%0], %1;" :: "r"(m), "r"(cnt) : "memory");
}
__device__ __forceinline__ void mbar_expect_tx(uint32_t m, unsigned bytes) {
    asm volatile("mbarrier.arrive.expect_tx.shared.b64 _, [%0], %1;"
                 :: "r"(m), "r"(bytes) : "memory");
}
__device__ __forceinline__ void mbar_wait(uint32_t m, int phase) {
    asm volatile(
        "{\n\t.reg .pred P;\n\t"
        "LW_%=:\n\t"
        "mbarrier.try_wait.parity.acquire.cta.shared::cta.b64 P, [%0], %1, 0x989680;\n\t"
        "@P bra LD_%=;\n\t"
        "bra LW_%=;\n\t"
        "LD_%=:\n\t}"
        :: "r"(m), "r"(phase) : "memory");
}
__device__ __forceinline__ void bulk_g2s(uint32_t dst, const void* src,
                                         unsigned bytes, uint32_t mbar) {
    asm volatile(
        "cp.async.bulk.shared::cluster.global.mbarrier::complete_tx::bytes "
        "[%0], [%1], %2, [%3];"
        :: "r"(dst), "l"(src), "r"(bytes), "r"(mbar) : "memory");
}

// ---------------------------------------------------------------------------
__global__ void k_init(const float* __restrict__ bih, const float* __restrict__ bhh) {
    int tid = blockIdx.x * blockDim.x + threadIdx.x;
    int nt  = gridDim.x * blockDim.x;
    if (tid < 2048) g_bias[tid] = bih[tid] + bhh[tid];
    for (int i = tid; i < 2 * 512 * 64; i += nt) g_h[i] = 0.0f;
    if (tid < NCTA) g_flags[tid] = 0u;
}

// ---------------------------------------------------------------------------
// Phase 1: xg[t][row][b] = sum_i W_ih[row][i] * x[b][t][i] + bias[row]
// (unchanged -- passing since R5)
// ---------------------------------------------------------------------------
__global__ void __launch_bounds__(256) k_inproj(const float* __restrict__ x,
                                                const float* __restrict__ Wih) {
    __shared__ __align__(16) float As[16 * 132];
    __shared__ __align__(16) float Bs[16 * 66];

    const int tid = threadIdx.x;
    const int bx  = blockIdx.x;
    const int t   = blockIdx.y;
    const int tr  = tid >> 4, tc = tid & 15;
    const int r0  = tr * 8,  c0 = tc * 4;
    const int kkg = tid & 3;
    const int bb  = tid >> 2;

    ull acc[8][2];
#pragma unroll
    for (int i = 0; i < 8; i++) { acc[i][0] = 0ull; acc[i][1] = 0ull; }

    for (int k0 = 0; k0 < 256; k0 += 16) {
#pragma unroll
        for (int j = 0; j < 2; j++) {
            int rr = (tid >> 2) + j * 64;
            float4 av = *(const float4*)(Wih + (size_t)(bx * 128 + rr) * 256 + k0 + kkg * 4);
            As[(kkg * 4 + 0) * 132 + rr] = av.x;
            As[(kkg * 4 + 1) * 132 + rr] = av.y;
            As[(kkg * 4 + 2) * 132 + rr] = av.z;
            As[(kkg * 4 + 3) * 132 + rr] = av.w;
        }
        {
            float4 bv = *(const float4*)(x + ((size_t)bb * 2048 + t) * 256 + k0 + kkg * 4);
            Bs[(kkg * 4 + 0) * 66 + bb] = bv.x;
            Bs[(kkg * 4 + 1) * 66 + bb] = bv.y;
            Bs[(kkg * 4 + 2) * 66 + bb] = bv.z;
            Bs[(kkg * 4 + 3) * 66 + bb] = bv.w;
        }
        __syncthreads();
#pragma unroll
        for (int k = 0; k < 16; k++) {
            float4 a0 = *(const float4*)&As[k * 132 + r0];
            float4 a1 = *(const float4*)&As[k * 132 + r0 + 4];
            ull b0 = *(const ull*)&Bs[k * 66 + c0];
            ull b1 = *(const ull*)&Bs[k * 66 + c0 + 2];
            ull sp;
            sp = splat2(a0.x); acc[0][0] = fma2(sp, b0, acc[0][0]); acc[0][1] = fma2(sp, b1, acc[0][1]);
            sp = splat2(a0.y); acc[1][0] = fma2(sp, b0, acc[1][0]); acc[1][1] = fma2(sp, b1, acc[1][1]);
            sp = splat2(a0.z); acc[2][0] = fma2(sp, b0, acc[2][0]); acc[2][1] = fma2(sp, b1, acc[2][1]);
            sp = splat2(a0.w); acc[3][0] = fma2(sp, b0, acc[3][0]); acc[3][1] = fma2(sp, b1, acc[3][1]);
            sp = splat2(a1.x); acc[4][0] = fma2(sp, b0, acc[4][0]); acc[4][1] = fma2(sp, b1, acc[4][1]);
            sp = splat2(a1.y); acc[5][0] = fma2(sp, b0, acc[5][0]); acc[5][1] = fma2(sp, b1, acc[5][1]);
            sp = splat2(a1.z); acc[6][0] = fma2(sp, b0, acc[6][0]); acc[6][1] = fma2(sp, b1, acc[6][1]);
            sp = splat2(a1.w); acc[7][0] = fma2(sp, b0, acc[7][0]); acc[7][1] = fma2(sp, b1, acc[7][1]);
        }
        __syncthreads();
    }
#pragma unroll
    for (int i = 0; i < 8; i++) {
        int row = bx * 128 + r0 + i;
        float bias = g_bias[row];
        float p0, p1, p2, p3;
        upk2(acc[i][0], p0, p1);
        upk2(acc[i][1], p2, p3);
        *(float4*)(g_xg + ((size_t)t * 2048 + row) * 64 + c0) =
            make_float4(p0 + bias, p1 + bias, p2 + bias, p3 + bias);
    }
}

// ---------------------------------------------------------------------------
// Phase 2: persistent recurrence, 128 CTAs x 256 threads, 1 CTA/SM.
// CTA owns 4 hidden units -> 16 gate rows (rl = unit*4 + gate).
// smem: Wt2 = pre-splatted {w,w} ull [512 k][16 rows]        = 64 KB
//       hs  = full h [512 k][64 b], TMA-filled in 4 chunks   = 128 KB
//       gp  = warp-group partials [4][16][64]                = 16 KB
// Sync: per-CTA g_flags (release store after hout). Consumer warp w<4 polls
// the 32 producer flags of chunk w (coalesced 128B line), then lane0 fences
// and issues that chunk's TMA. GEMM phases gate on the chunk mbars.
// Warp (q = wid&3) covers k-sub [q*32,+32) per phase, ch = wid>>2 col half.
// Lane (rg = lane>>3, cg = lane&7): 4 rows x 4 cols.
// ---------------------------------------------------------------------------
__global__ void __launch_bounds__(256, 1) k_rec(const float* __restrict__ Whh) {
    extern __shared__ __align__(16) char smraw[];
    ull*   Wt2 = (ull*)smraw;                          // 512*16 ull = 65536 B
    float* hs  = (float*)(smraw + 65536);              // 512*64 fl  = 131072 B
    float* gp  = (float*)(smraw + 65536 + 131072);     // 4*16*64 fl = 16384 B
    __shared__ __align__(8) ull mbars[4];

    const int tid  = threadIdx.x;
    const int h0   = blockIdx.x * 4;
    const int wid  = tid >> 5, lane = tid & 31;
    const int q    = wid & 3;                 // k-sub within each chunk
    const int ch   = wid >> 2;                // col half
    const int rg   = lane >> 3, cg = lane & 7;
    const int r0   = rg * 4;                  // 4 rows
    const int c0   = ch * 32 + cg * 4;        // 4 cols
    const int u2   = tid >> 6, b = tid & 63;  // cell-update mapping

    const uint32_t hs_u = s2u(hs);

    // fill pre-splatted W slab: Wt2[k*16 + rl] = {w,w},
    // w = Whh[(rl&3)*512 + h0 + (rl>>2)][k]
#pragma unroll
    for (int j = 0; j < 8; j++) {
        int flat = tid + j * 256;              // float4 idx 0..2047
        int rl = flat >> 7, k4 = flat & 127;
        int grw = (rl & 3) * 512 + h0 + (rl >> 2);
        float4 w4 = *(const float4*)(Whh + (size_t)grw * 512 + k4 * 4);
        Wt2[(k4 * 4 + 0) * 16 + rl] = splat2(w4.x);
        Wt2[(k4 * 4 + 1) * 16 + rl] = splat2(w4.y);
        Wt2[(k4 * 4 + 2) * 16 + rl] = splat2(w4.z);
        Wt2[(k4 * 4 + 3) * 16 + rl] = splat2(w4.w);
    }
    if (tid == 0) {
#pragma unroll
        for (int p = 0; p < 4; p++) mbar_init(s2u(&mbars[p]), 1u);
    }
    float cstate = 0.0f;
    __syncthreads();

    for (int s = 0; s < TSZ; s++) {
        const float* hin  = g_h + (s & 1) * 32768;
        float*       hout = g_h + ((s + 1) & 1) * 32768;
        const int    ph   = s & 1;            // mbar parity (1 use per step)

        // xg for this thread's cell (independent of h; overlaps everything)
        float xgi = __ldcs(g_xg + ((size_t)s * 2048 + 0 * 512 + h0 + u2) * 64 + b);
        float xgf = __ldcs(g_xg + ((size_t)s * 2048 + 1 * 512 + h0 + u2) * 64 + b);
        float xgg = __ldcs(g_xg + ((size_t)s * 2048 + 2 * 512 + h0 + u2) * 64 + b);
        float xgo = __ldcs(g_xg + ((size_t)s * 2048 + 3 * 512 + h0 + u2) * 64 + b);

        // ---- chunk gating: warp w polls chunk w's 32 producers, then
        //      lane0 issues that chunk's TMA (independent per chunk) -------
        if (wid < 4) {
            const unsigned target = (unsigned)s;
            const unsigned* f = g_flags + wid * 32 + lane;   // coalesced line
            unsigned v;
            do {
                asm volatile("ld.relaxed.gpu.global.u32 %0,[%1];"
                             : "=r"(v) : "l"(f));
            } while (v < target);
            __syncwarp();
            if (lane == 0) {
                asm volatile("fence.acq_rel.gpu;" ::: "memory");
                asm volatile("fence.proxy.async;" ::: "memory");
                uint32_t m = s2u(&mbars[wid]);
                mbar_expect_tx(m, 32768u);
                bulk_g2s(hs_u + wid * 32768u, hin + wid * 8192, 32768u, m);
            }
        }
        // (no __syncthreads: consumers gate on the chunk mbarriers)

        // ---- GEMM: 4 phases of 128 k; warp q takes 32 k per phase --------
        ull a00 = 0, a01 = 0, a10 = 0, a11 = 0;
        ull a20 = 0, a21 = 0, a30 = 0, a31 = 0;
#pragma unroll
        for (int p = 0; p < 4; p++) {
            mbar_wait(s2u(&mbars[p]), ph);
            const int kbeg = p * 128 + q * 32;
            const ull*   wp = Wt2 + kbeg * 16;
            const float* hp = hs + kbeg * 64 + c0;
#pragma unroll
            for (int k = 0; k < 32; k++) {
                ulonglong2 wa = *(const ulonglong2*)(wp + k * 16 + r0);     // rows r0,r0+1
                ulonglong2 wb = *(const ulonglong2*)(wp + k * 16 + r0 + 2); // rows r0+2,+3
                ulonglong2 hv = *(const ulonglong2*)(hp + k * 64);          // cols c0..+3
                a00 = fma2(wa.x, hv.x, a00); a01 = fma2(wa.x, hv.y, a01);
                a10 = fma2(wa.y, hv.x, a10); a11 = fma2(wa.y, hv.y, a11);
                a20 = fma2(wb.x, hv.x, a20); a21 = fma2(wb.x, hv.y, a21);
                a30 = fma2(wb.y, hv.x, a30); a31 = fma2(wb.y, hv.y, a31);
            }
        }
        // write warp-group partials
        {
            float* gq = gp + (q * 16) * 64;
            *(ulonglong2*)(gq + (r0 + 0) * 64 + c0) = make_ulonglong2(a00, a01);
            *(ulonglong2*)(gq + (r0 + 1) * 64 + c0) = make_ulonglong2(a10, a11);
            *(ulonglong2*)(gq + (r0 + 2) * 64 + c0) = make_ulonglong2(a20, a21);
            *(ulonglong2*)(gq + (r0 + 3) * 64 + c0) = make_ulonglong2(a30, a31);
        }
        __syncthreads();

        // ---- reduce partials + cell update (one cell per thread) --------
        {
            int rI = u2 * 4 + 0, rF = u2 * 4 + 1, rG = u2 * 4 + 2, rO = u2 * 4 + 3;
            float gi = xgi, gf = xgf, gg = xgg, go = xgo;
#pragma unroll
            for (int qq = 0; qq < 4; qq++) {
                const float* gq = gp + (qq * 16) * 64;
                gi += gq[rI * 64 + b];
                gf += gq[rF * 64 + b];
                gg += gq[rG * 64 + b];
                go += gq[rO * 64 + b];
            }
            float ig = fsig(gi), fg = fsig(gf), gt = ftanh(gg), og = fsig(go);
            cstate = fg * cstate + ig * gt;
            float hv = og * ftanh(cstate);
            asm volatile("st.global.cg.f32 [%0], %1;"
                         :: "l"(hout + (h0 + u2) * 64 + b), "f"(hv) : "memory");
        }
        __syncthreads();   // all hout stores issued + all hs reads done

        // ---- publish: per-CTA release store (no contention) -------------
        if (tid == 0) {
            asm volatile("fence.acq_rel.gpu;" ::: "memory");
            asm volatile("st.relaxed.gpu.global.u32 [%0],%1;"
                         :: "l"(g_flags + blockIdx.x), "r"(s + 1) : "memory");
        }
    }
}

// ---------------------------------------------------------------------------
// FC head: out[b][o] = sum_h h_last[h][b] * W_fc[o][h] + b_fc[o]
// warp-per-output, shfl reduction. h_last = g_h buffer 0.
// ---------------------------------------------------------------------------
__global__ void __launch_bounds__(256) k_fc(const float* __restrict__ Wfc,
                                            const float* __restrict__ bfc,
                                            float* __restrict__ out) {
    int g    = blockIdx.x * 8 + (threadIdx.x >> 5);
    int lane = threadIdx.x & 31;
    int o = g >> 6, b = g & 63;
    float s = 0.0f;
#pragma unroll
    for (int j = 0; j < 16; j++) {
        int h = lane + j * 32;
        s += g_h[h * 64 + b] * Wfc[o * 512 + h];
    }
#pragma unroll
    for (int m = 16; m > 0; m >>= 1)
        s += __shfl_xor_sync(0xFFFFFFFFu, s, m);
    if (lane == 0) out[b * 10 + o] = s + bfc[o];
}

// ---------------------------------------------------------------------------
extern "C" void kernel_launch(void* const* d_in, const int* in_sizes, int n_in,
                              void* d_out, int out_size) {
    const float* x    = (const float*)d_in[0];
    const float* W_ih = (const float*)d_in[1];
    const float* W_hh = (const float*)d_in[2];
    const float* b_ih = (const float*)d_in[3];
    const float* b_hh = (const float*)d_in[4];
    const float* W_fc = (const float*)d_in[5];
    const float* b_fc = (const float*)d_in[6];
    float* out = (float*)d_out;

    const int SMEM_REC = 65536 + 131072 + 16384;   // 212992 B (<227KB cap)
    cudaFuncSetAttribute(k_rec, cudaFuncAttributeMaxDynamicSharedMemorySize, SMEM_REC);

    k_init<<<64, 256>>>(b_ih, b_hh);
    k_inproj<<<dim3(16, 2048), 256>>>(x, W_ih);
    k_rec<<<NCTA, 256, SMEM_REC>>>(W_hh);
    k_fc<<<80, 256>>>(W_fc, b_fc, out);
}

// round 15
// speedup vs baseline: 1.0969x; 1.0969x over previous
#include <cuda_runtime.h>
#include <cstdint>
#include <cstddef>
#include <math.h>

// ---------------------------------------------------------------------------
// LSTM  I=256 H=512 O=10 B=64 T=2048  (fp32, f32x2 packed-FMA pipe)
// R15: two phase-shifted independent recurrences (batch halves A=0..31,
//      B=32..63) interleaved per tick. Each group's publish->poll round trip
//      and TMA fill hides under the OTHER group's GEMM+epilogue. All R13
//      primitives kept: single counter per group, tid0-only poll, RED
//      publish, 4x16KB TMA chunks, mbar parity gating, identical Wt2 pack.
// ---------------------------------------------------------------------------

#define TSZ  2048
#define NCTA 128

typedef unsigned long long ull;

// scratch (__device__ globals are the sanctioned scratch mechanism)
__device__ float    g_xg[268435456];     // 1 GiB: [T][4H][B]  (2048*2048*64)
__device__ float    g_h[2 * 2 * 16384];  // [buf][grp][512 h][32 b]
__device__ float    g_bias[2048];        // b_ih + b_hh
__device__ unsigned g_cntA;              // group-A barrier counter
__device__ unsigned g_cntB;              // group-B barrier counter

// ---- packed f32x2 helpers (Blackwell dual-fp32 pipe) ----------------------
__device__ __forceinline__ ull splat2(float a) {
    ull r; asm("mov.b64 %0,{%1,%1};" : "=l"(r) : "f"(a)); return r;
}
__device__ __forceinline__ ull fma2(ull a, ull b, ull c) {
    ull d; asm("fma.rn.f32x2 %0,%1,%2,%3;" : "=l"(d) : "l"(a), "l"(b), "l"(c));
    return d;
}
__device__ __forceinline__ void upk2(ull v, float& a, float& b) {
    asm("mov.b64 {%0,%1},%2;" : "=f"(a), "=f"(b) : "l"(v));
}

// fast activations (rel err ~1e-6; budget 1e-3)
__device__ __forceinline__ float fsig(float x) {
    return __fdividef(1.0f, 1.0f + __expf(-x));
}
__device__ __forceinline__ float ftanh(float x) {
    return 1.0f - __fdividef(2.0f, __expf(2.0f * x) + 1.0f);
}

// ---- smem / mbarrier / bulk-copy helpers ----------------------------------
__device__ __forceinline__ uint32_t s2u(const void* p) {
    uint32_t a;
    asm("{ .reg .u64 t; cvta.to.shared.u64 t, %1; cvt.u32.u64 %0, t; }"
        : "=r"(a) : "l"(p));
    return a;
}
__device__ __forceinline__ void mbar_init(uint32_t m, unsigned cnt) {
    asm volatile("mbarrier.init.shared.b64 [%0], %1;" :: "r"(m), "r"(cnt) : "memory");
}
__device__ __forceinline__ void mbar_expect_tx(uint32_t m, unsigned bytes) {
    asm volatile("mbarrier.arrive.expect_tx.shared.b64 _, [%0], %1;"
                 :: "r"(m), "r"(bytes) : "memory");
}
__device__ __forceinline__ void mbar_wait(uint32_t m, int phase) {
    asm volatile(
        "{\n\t.reg .pred P;\n\t"
        "LW_%=:\n\t"
        "mbarrier.try_wait.parity.acquire.cta.shared::cta.b64 P, [%0], %1, 0x989680;\n\t"
        "@P bra LD_%=;\n\t"
        "bra LW_%=;\n\t"
        "LD_%=:\n\t}"
        :: "r"(m), "r"(phase) : "memory");
}
__device__ __forceinline__ void bulk_g2s(uint32_t dst, const void* src,
                                         unsigned bytes, uint32_t mbar) {
    asm volatile(
        "cp.async.bulk.shared::cluster.global.mbarrier::complete_tx::bytes "
        "[%0], [%1], %2, [%3];"
        :: "r"(dst), "l"(src), "r"(bytes), "r"(mbar) : "memory");
}
__device__ __forceinline__ void poll_counter(const unsigned* c, unsigned target) {
    unsigned v;
    do {
        asm volatile("ld.relaxed.gpu.global.u32 %0,[%1];" : "=r"(v) : "l"(c));
    } while (v < target);
    asm volatile("fence.acq_rel.gpu;" ::: "memory");
}

// ---------------------------------------------------------------------------
__global__ void k_init(const float* __restrict__ bih, const float* __restrict__ bhh) {
    int tid = blockIdx.x * blockDim.x + threadIdx.x;
    int nt  = gridDim.x * blockDim.x;
    if (tid < 2048) g_bias[tid] = bih[tid] + bhh[tid];
    for (int i = tid; i < 2 * 2 * 16384; i += nt) g_h[i] = 0.0f;
    if (tid == 0) { g_cntA = 0u; g_cntB = 0u; }
}

// ---------------------------------------------------------------------------
// Phase 1: xg[t][row][b] = sum_i W_ih[row][i] * x[b][t][i] + bias[row]
// (unchanged -- passing since R5)
// ---------------------------------------------------------------------------
__global__ void __launch_bounds__(256) k_inproj(const float* __restrict__ x,
                                                const float* __restrict__ Wih) {
    __shared__ __align__(16) float As[16 * 132];
    __shared__ __align__(16) float Bs[16 * 66];

    const int tid = threadIdx.x;
    const int bx  = blockIdx.x;
    const int t   = blockIdx.y;
    const int tr  = tid >> 4, tc = tid & 15;
    const int r0  = tr * 8,  c0 = tc * 4;
    const int kkg = tid & 3;
    const int bb  = tid >> 2;

    ull acc[8][2];
#pragma unroll
    for (int i = 0; i < 8; i++) { acc[i][0] = 0ull; acc[i][1] = 0ull; }

    for (int k0 = 0; k0 < 256; k0 += 16) {
#pragma unroll
        for (int j = 0; j < 2; j++) {
            int rr = (tid >> 2) + j * 64;
            float4 av = *(const float4*)(Wih + (size_t)(bx * 128 + rr) * 256 + k0 + kkg * 4);
            As[(kkg * 4 + 0) * 132 + rr] = av.x;
            As[(kkg * 4 + 1) * 132 + rr] = av.y;
            As[(kkg * 4 + 2) * 132 + rr] = av.z;
            As[(kkg * 4 + 3) * 132 + rr] = av.w;
        }
        {
            float4 bv = *(const float4*)(x + ((size_t)bb * 2048 + t) * 256 + k0 + kkg * 4);
            Bs[(kkg * 4 + 0) * 66 + bb] = bv.x;
            Bs[(kkg * 4 + 1) * 66 + bb] = bv.y;
            Bs[(kkg * 4 + 2) * 66 + bb] = bv.z;
            Bs[(kkg * 4 + 3) * 66 + bb] = bv.w;
        }
        __syncthreads();
#pragma unroll
        for (int k = 0; k < 16; k++) {
            float4 a0 = *(const float4*)&As[k * 132 + r0];
            float4 a1 = *(const float4*)&As[k * 132 + r0 + 4];
            ull b0 = *(const ull*)&Bs[k * 66 + c0];
            ull b1 = *(const ull*)&Bs[k * 66 + c0 + 2];
            ull sp;
            sp = splat2(a0.x); acc[0][0] = fma2(sp, b0, acc[0][0]); acc[0][1] = fma2(sp, b1, acc[0][1]);
            sp = splat2(a0.y); acc[1][0] = fma2(sp, b0, acc[1][0]); acc[1][1] = fma2(sp, b1, acc[1][1]);
            sp = splat2(a0.z); acc[2][0] = fma2(sp, b0, acc[2][0]); acc[2][1] = fma2(sp, b1, acc[2][1]);
            sp = splat2(a0.w); acc[3][0] = fma2(sp, b0, acc[3][0]); acc[3][1] = fma2(sp, b1, acc[3][1]);
            sp = splat2(a1.x); acc[4][0] = fma2(sp, b0, acc[4][0]); acc[4][1] = fma2(sp, b1, acc[4][1]);
            sp = splat2(a1.y); acc[5][0] = fma2(sp, b0, acc[5][0]); acc[5][1] = fma2(sp, b1, acc[5][1]);
            sp = splat2(a1.z); acc[6][0] = fma2(sp, b0, acc[6][0]); acc[6][1] = fma2(sp, b1, acc[6][1]);
            sp = splat2(a1.w); acc[7][0] = fma2(sp, b0, acc[7][0]); acc[7][1] = fma2(sp, b1, acc[7][1]);
        }
        __syncthreads();
    }
#pragma unroll
    for (int i = 0; i < 8; i++) {
        int row = bx * 128 + r0 + i;
        float bias = g_bias[row];
        float p0, p1, p2, p3;
        upk2(acc[i][0], p0, p1);
        upk2(acc[i][1], p2, p3);
        *(float4*)(g_xg + ((size_t)t * 2048 + row) * 64 + c0) =
            make_float4(p0 + bias, p1 + bias, p2 + bias, p3 + bias);
    }
}

// ---------------------------------------------------------------------------
// Phase 2: persistent recurrence, 128 CTAs x 256 threads, 1 CTA/SM.
// CTA owns 4 hidden units -> 16 gate rows. Two batch groups (A: b0..31,
// B: b32..63) processed phase-shifted within each tick.
// smem: Wt2 64KB (pre-splatted, SHARED by both groups)
//       hsA/hsB 64KB each ([512 k][32 b], TMA-filled, 4x16KB chunks)
//       gpA/gpB 8KB each (k-quarter partials [4][16][32])
// GEMM tile per group: warp (q=wid&3 k-sub, ch=wid>>2 col half of 32);
// lane: 2 rows (r0=(lane>>2)*2) x 4 cols (c0=ch*16+(lane&3)*4).
// ---------------------------------------------------------------------------
__global__ void __launch_bounds__(256, 1) k_rec(const float* __restrict__ Whh) {
    extern __shared__ __align__(16) char smraw[];
    ull*   Wt2 = (ull*)smraw;                          // 65536 B
    float* hsA = (float*)(smraw + 65536);              // 65536 B
    float* hsB = (float*)(smraw + 131072);             // 65536 B
    float* gpA = (float*)(smraw + 196608);             //  8192 B
    float* gpB = (float*)(smraw + 204800);             //  8192 B
    __shared__ __align__(8) ull mbA[4], mbB[4];

    const int tid  = threadIdx.x;
    const int h0   = blockIdx.x * 4;
    const int wid  = tid >> 5, lane = tid & 31;
    const int q    = wid & 3;                 // k-sub within each chunk
    const int ch   = wid >> 2;                // col half (of 32)
    const int r0   = (lane >> 2) * 2;         // 2 rows (even base)
    const int c0   = ch * 16 + (lane & 3) * 4;// 4 cols
    // cell mapping: tid<128 -> group A, else group B
    const int grp  = tid >> 7;                // 0 = A, 1 = B
    const int tl   = tid & 127;
    const int cu   = tl >> 5;                 // hidden unit 0..3
    const int cb   = tl & 31;                 // batch within group
    const int bglob = grp * 32 + cb;

    const uint32_t hsA_u = s2u(hsA), hsB_u = s2u(hsB);

    // fill pre-splatted W slab (byte-identical to R13, proven)
#pragma unroll
    for (int j = 0; j < 8; j++) {
        int flat = tid + j * 256;
        int rl = flat >> 7, k4 = flat & 127;
        int grw = (rl & 3) * 512 + h0 + (rl >> 2);
        float4 w4 = *(const float4*)(Whh + (size_t)grw * 512 + k4 * 4);
        Wt2[(k4 * 4 + 0) * 16 + rl] = splat2(w4.x);
        Wt2[(k4 * 4 + 1) * 16 + rl] = splat2(w4.y);
        Wt2[(k4 * 4 + 2) * 16 + rl] = splat2(w4.z);
        Wt2[(k4 * 4 + 3) * 16 + rl] = splat2(w4.w);
    }
    if (tid == 0) {
#pragma unroll
        for (int p = 0; p < 4; p++) { mbar_init(s2u(&mbA[p]), 1u); mbar_init(s2u(&mbB[p]), 1u); }
        asm volatile("fence.proxy.async;" ::: "memory");
    }
    float cstate = 0.0f;
    __syncthreads();

    for (int s = 0; s < TSZ; s++) {
        const int bufIn  = s & 1;
        const int bufOut = (s + 1) & 1;
        const int ph     = s & 1;
        const float* hinA = g_h + bufIn * 32768;           // grp A base
        const float* hinB = g_h + bufIn * 32768 + 16384;   // grp B base
        float* houtA = g_h + bufOut * 32768;
        float* houtB = g_h + bufOut * 32768 + 16384;
        const unsigned target = (unsigned)s * NCTA;

        // xg for this thread's OWN cell (used in its group's epilogue)
        float xgi = __ldcs(g_xg + ((size_t)s * 2048 + 0 * 512 + h0 + cu) * 64 + bglob);
        float xgf = __ldcs(g_xg + ((size_t)s * 2048 + 1 * 512 + h0 + cu) * 64 + bglob);
        float xgg = __ldcs(g_xg + ((size_t)s * 2048 + 2 * 512 + h0 + cu) * 64 + bglob);
        float xgo = __ldcs(g_xg + ((size_t)s * 2048 + 3 * 512 + h0 + cu) * 64 + bglob);

        // ---- group A: wait producers (published ~1 tick ago) + TMA -------
        if (tid == 0) {
            poll_counter(&g_cntA, target);
            asm volatile("fence.proxy.async;" ::: "memory");
#pragma unroll
            for (int c = 0; c < 4; c++) {
                uint32_t m = s2u(&mbA[c]);
                mbar_expect_tx(m, 16384u);
                bulk_g2s(hsA_u + c * 16384u, hinA + c * 4096, 16384u, m);
            }
        }

        // ---- GEMM A (16 x 32 x 512) --------------------------------------
        ull a00 = 0, a01 = 0, a10 = 0, a11 = 0;
#pragma unroll
        for (int p = 0; p < 4; p++) {
            mbar_wait(s2u(&mbA[p]), ph);
            const int kbeg = p * 128 + q * 32;
            const ull*   wp = Wt2 + kbeg * 16;
            const float* hp = hsA + kbeg * 32 + c0;
#pragma unroll
            for (int k = 0; k < 32; k++) {
                ulonglong2 wa = *(const ulonglong2*)(wp + k * 16 + r0);
                ulonglong2 hv = *(const ulonglong2*)(hp + k * 32);
                a00 = fma2(wa.x, hv.x, a00); a01 = fma2(wa.x, hv.y, a01);
                a10 = fma2(wa.y, hv.x, a10); a11 = fma2(wa.y, hv.y, a11);
            }
        }
        {
            float* gq = gpA + q * 512;     // [16][32]
            *(ulonglong2*)(gq + (r0 + 0) * 32 + c0) = make_ulonglong2(a00, a01);
            *(ulonglong2*)(gq + (r0 + 1) * 32 + c0) = make_ulonglong2(a10, a11);
        }

        // ---- group B: poll + TMA now -> fill hides under epi_A -----------
        if (tid == 0) {
            poll_counter(&g_cntB, target);
            asm volatile("fence.proxy.async;" ::: "memory");
#pragma unroll
            for (int c = 0; c < 4; c++) {
                uint32_t m = s2u(&mbB[c]);
                mbar_expect_tx(m, 16384u);
                bulk_g2s(hsB_u + c * 16384u, hinB + c * 4096, 16384u, m);
            }
        }
        __syncthreads();

        // ---- cells A (tid < 128) -----------------------------------------
        if (grp == 0) {
            float gi = xgi, gf = xgf, gg = xgg, go = xgo;
#pragma unroll
            for (int qq = 0; qq < 4; qq++) {
                const float* gq = gpA + qq * 512;
                gi += gq[(cu * 4 + 0) * 32 + cb];
                gf += gq[(cu * 4 + 1) * 32 + cb];
                gg += gq[(cu * 4 + 2) * 32 + cb];
                go += gq[(cu * 4 + 3) * 32 + cb];
            }
            float ig = fsig(gi), fg = fsig(gf), gt = ftanh(gg), og = fsig(go);
            cstate = fg * cstate + ig * gt;
            float hv = og * ftanh(cstate);
            asm volatile("st.global.cg.f32 [%0], %1;"
                         :: "l"(houtA + (h0 + cu) * 32 + cb), "f"(hv) : "memory");
        }
        __syncthreads();
        if (tid == 0) {
            asm volatile("fence.acq_rel.gpu;" ::: "memory");
            asm volatile("red.relaxed.gpu.global.add.u32 [%0], %1;"
                         :: "l"(&g_cntA), "r"(1u) : "memory");
        }

        // ---- GEMM B (16 x 32 x 512) --------------------------------------
        a00 = 0; a01 = 0; a10 = 0; a11 = 0;
#pragma unroll
        for (int p = 0; p < 4; p++) {
            mbar_wait(s2u(&mbB[p]), ph);
            const int kbeg = p * 128 + q * 32;
            const ull*   wp = Wt2 + kbeg * 16;
            const float* hp = hsB + kbeg * 32 + c0;
#pragma unroll
            for (int k = 0; k < 32; k++) {
                ulonglong2 wa = *(const ulonglong2*)(wp + k * 16 + r0);
                ulonglong2 hv = *(const ulonglong2*)(hp + k * 32);
                a00 = fma2(wa.x, hv.x, a00); a01 = fma2(wa.x, hv.y, a01);
                a10 = fma2(wa.y, hv.x, a10); a11 = fma2(wa.y, hv.y, a11);
            }
        }
        {
            float* gq = gpB + q * 512;
            *(ulonglong2*)(gq + (r0 + 0) * 32 + c0) = make_ulonglong2(a00, a01);
            *(ulonglong2*)(gq + (r0 + 1) * 32 + c0) = make_ulonglong2(a10, a11);
        }
        __syncthreads();

        // ---- cells B (tid >= 128) ----------------------------------------
        if (grp == 1) {
            float gi = xgi, gf = xgf, gg = xgg, go = xgo;
#pragma unroll
            for (int qq = 0; qq < 4; qq++) {
                const float* gq = gpB + qq * 512;
                gi += gq[(cu * 4 + 0) * 32 + cb];
                gf += gq[(cu * 4 + 1) * 32 + cb];
                gg += gq[(cu * 4 + 2) * 32 + cb];
                go += gq[(cu * 4 + 3) * 32 + cb];
            }
            float ig = fsig(gi), fg = fsig(gf), gt = ftanh(gg), og = fsig(go);
            cstate = fg * cstate + ig * gt;
            float hv = og * ftanh(cstate);
            asm volatile("st.global.cg.f32 [%0], %1;"
                         :: "l"(houtB + (h0 + cu) * 32 + cb), "f"(hv) : "memory");
        }
        __syncthreads();
        if (tid == 0) {
            asm volatile("fence.acq_rel.gpu;" ::: "memory");
            asm volatile("red.relaxed.gpu.global.add.u32 [%0], %1;"
                         :: "l"(&g_cntB), "r"(1u) : "memory");
        }
    }
}

// ---------------------------------------------------------------------------
// FC head: out[b][o] = sum_h h_last[h][b] * W_fc[o][h] + b_fc[o]
// h_last = g_h buffer 0, layout [grp][512][32].
// ---------------------------------------------------------------------------
__global__ void __launch_bounds__(256) k_fc(const float* __restrict__ Wfc,
                                            const float* __restrict__ bfc,
                                            float* __restrict__ out) {
    int g    = blockIdx.x * 8 + (threadIdx.x >> 5);
    int lane = threadIdx.x & 31;
    int o = g >> 6, b = g & 63;
    const float* hbase = g_h + (b >> 5) * 16384;   // group base (buffer 0)
    int bl = b & 31;
    float s = 0.0f;
#pragma unroll
    for (int j = 0; j < 16; j++) {
        int h = lane + j * 32;
        s += hbase[h * 32 + bl] * Wfc[o * 512 + h];
    }
#pragma unroll
    for (int m = 16; m > 0; m >>= 1)
        s += __shfl_xor_sync(0xFFFFFFFFu, s, m);
    if (lane == 0) out[b * 10 + o] = s + bfc[o];
}

// ---------------------------------------------------------------------------
extern "C" void kernel_launch(void* const* d_in, const int* in_sizes, int n_in,
                              void* d_out, int out_size) {
    const float* x    = (const float*)d_in[0];
    const float* W_ih = (const float*)d_in[1];
    const float* W_hh = (const float*)d_in[2];
    const float* b_ih = (const float*)d_in[3];
    const float* b_hh = (const float*)d_in[4];
    const float* W_fc = (const float*)d_in[5];
    const float* b_fc = (const float*)d_in[6];
    float* out = (float*)d_out;

    const int SMEM_REC = 65536 * 3 + 8192 * 2;   // 212992 B (<227KB cap)
    cudaFuncSetAttribute(k_rec, cudaFuncAttributeMaxDynamicSharedMemorySize, SMEM_REC);

    k_init<<<64, 256>>>(b_ih, b_hh);
    k_inproj<<<dim3(16, 2048), 256>>>(x, W_ih);
    k_rec<<<NCTA, 256, SMEM_REC>>>(W_hh);
    k_fc<<<80, 256>>>(W_fc, b_fc, out);
}

// round 16
// speedup vs baseline: 1.2045x; 1.0981x over previous
#include <cuda_runtime.h>
#include <cstdint>
#include <cstddef>
#include <math.h>

// ---------------------------------------------------------------------------
// LSTM  I=256 H=512 O=10 B=64 T=2048  (fp32, f32x2 packed-FMA pipe)
// R16: R13 (16.33ms) with the single chip counter split into 4 per-group
//      counters (group p = CTAs [32p,32p+32) = producers of h chunk p).
//      tid0 interleaves poll(p) -> TMA(chunk p): chunk 0 gates on 32 CTAs
//      instead of 128, and later groups' stragglers hide under compute.
//      Sync shape preserved: tid0-only poll, 1 line/poll, RED publish.
// ---------------------------------------------------------------------------

#define TSZ  2048
#define NCTA 128

typedef unsigned long long ull;

// scratch (__device__ globals are the sanctioned scratch mechanism)
__device__ float    g_xg[268435456];     // 1 GiB: [T][4H][B]  (2048*2048*64)
__device__ float    g_h[2 * 512 * 64];   // double-buffered h: [H][B]
__device__ float    g_bias[2048];        // b_ih + b_hh
__device__ unsigned g_cnt4[4];           // per-group step counters

// ---- packed f32x2 helpers (Blackwell dual-fp32 pipe) ----------------------
__device__ __forceinline__ ull splat2(float a) {
    ull r; asm("mov.b64 %0,{%1,%1};" : "=l"(r) : "f"(a)); return r;
}
__device__ __forceinline__ ull fma2(ull a, ull b, ull c) {
    ull d; asm("fma.rn.f32x2 %0,%1,%2,%3;" : "=l"(d) : "l"(a), "l"(b), "l"(c));
    return d;
}
__device__ __forceinline__ void upk2(ull v, float& a, float& b) {
    asm("mov.b64 {%0,%1},%2;" : "=f"(a), "=f"(b) : "l"(v));
}

// fast activations (rel err ~1e-6; budget 1e-3)
__device__ __forceinline__ float fsig(float x) {
    return __fdividef(1.0f, 1.0f + __expf(-x));
}
__device__ __forceinline__ float ftanh(float x) {
    return 1.0f - __fdividef(2.0f, __expf(2.0f * x) + 1.0f);
}

// ---- smem / mbarrier / bulk-copy helpers ----------------------------------
__device__ __forceinline__ uint32_t s2u(const void* p) {
    uint32_t a;
    asm("{ .reg .u64 t; cvta.to.shared.u64 t, %1; cvt.u32.u64 %0, t; }"
        : "=r"(a) : "l"(p));
    return a;
}
__device__ __forceinline__ void mbar_init(uint32_t m, unsigned cnt) {
    asm volatile("mbarrier.init.shared.b64 [%0], %1;" :: "r"(m), "r"(cnt) : "memory");
}
__device__ __forceinline__ void mbar_expect_tx(uint32_t m, unsigned bytes) {
    asm volatile("mbarrier.arrive.expect_tx.shared.b64 _, [%0], %1;"
                 :: "r"(m), "r"(bytes) : "memory");
}
__device__ __forceinline__ void mbar_wait(uint32_t m, int phase) {
    asm volatile(
        "{\n\t.reg .pred P;\n\t"
        "LW_%=:\n\t"
        "mbarrier.try_wait.parity.acquire.cta.shared::cta.b64 P, [%0], %1, 0x989680;\n\t"
        "@P bra LD_%=;\n\t"
        "bra LW_%=;\n\t"
        "LD_%=:\n\t}"
        :: "r"(m), "r"(phase) : "memory");
}
__device__ __forceinline__ void bulk_g2s(uint32_t dst, const void* src,
                                         unsigned bytes, uint32_t mbar) {
    asm volatile(
        "cp.async.bulk.shared::cluster.global.mbarrier::complete_tx::bytes "
        "[%0], [%1], %2, [%3];"
        :: "r"(dst), "l"(src), "r"(bytes), "r"(mbar) : "memory");
}

// ---------------------------------------------------------------------------
__global__ void k_init(const float* __restrict__ bih, const float* __restrict__ bhh) {
    int tid = blockIdx.x * blockDim.x + threadIdx.x;
    int nt  = gridDim.x * blockDim.x;
    if (tid < 2048) g_bias[tid] = bih[tid] + bhh[tid];
    for (int i = tid; i < 2 * 512 * 64; i += nt) g_h[i] = 0.0f;
    if (tid < 4) g_cnt4[tid] = 0u;
}

// ---------------------------------------------------------------------------
// Phase 1: xg[t][row][b] = sum_i W_ih[row][i] * x[b][t][i] + bias[row]
// (unchanged -- passing since R5)
// ---------------------------------------------------------------------------
__global__ void __launch_bounds__(256) k_inproj(const float* __restrict__ x,
                                                const float* __restrict__ Wih) {
    __shared__ __align__(16) float As[16 * 132];
    __shared__ __align__(16) float Bs[16 * 66];

    const int tid = threadIdx.x;
    const int bx  = blockIdx.x;
    const int t   = blockIdx.y;
    const int tr  = tid >> 4, tc = tid & 15;
    const int r0  = tr * 8,  c0 = tc * 4;
    const int kkg = tid & 3;
    const int bb  = tid >> 2;

    ull acc[8][2];
#pragma unroll
    for (int i = 0; i < 8; i++) { acc[i][0] = 0ull; acc[i][1] = 0ull; }

    for (int k0 = 0; k0 < 256; k0 += 16) {
#pragma unroll
        for (int j = 0; j < 2; j++) {
            int rr = (tid >> 2) + j * 64;
            float4 av = *(const float4*)(Wih + (size_t)(bx * 128 + rr) * 256 + k0 + kkg * 4);
            As[(kkg * 4 + 0) * 132 + rr] = av.x;
            As[(kkg * 4 + 1) * 132 + rr] = av.y;
            As[(kkg * 4 + 2) * 132 + rr] = av.z;
            As[(kkg * 4 + 3) * 132 + rr] = av.w;
        }
        {
            float4 bv = *(const float4*)(x + ((size_t)bb * 2048 + t) * 256 + k0 + kkg * 4);
            Bs[(kkg * 4 + 0) * 66 + bb] = bv.x;
            Bs[(kkg * 4 + 1) * 66 + bb] = bv.y;
            Bs[(kkg * 4 + 2) * 66 + bb] = bv.z;
            Bs[(kkg * 4 + 3) * 66 + bb] = bv.w;
        }
        __syncthreads();
#pragma unroll
        for (int k = 0; k < 16; k++) {
            float4 a0 = *(const float4*)&As[k * 132 + r0];
            float4 a1 = *(const float4*)&As[k * 132 + r0 + 4];
            ull b0 = *(const ull*)&Bs[k * 66 + c0];
            ull b1 = *(const ull*)&Bs[k * 66 + c0 + 2];
            ull sp;
            sp = splat2(a0.x); acc[0][0] = fma2(sp, b0, acc[0][0]); acc[0][1] = fma2(sp, b1, acc[0][1]);
            sp = splat2(a0.y); acc[1][0] = fma2(sp, b0, acc[1][0]); acc[1][1] = fma2(sp, b1, acc[1][1]);
            sp = splat2(a0.z); acc[2][0] = fma2(sp, b0, acc[2][0]); acc[2][1] = fma2(sp, b1, acc[2][1]);
            sp = splat2(a0.w); acc[3][0] = fma2(sp, b0, acc[3][0]); acc[3][1] = fma2(sp, b1, acc[3][1]);
            sp = splat2(a1.x); acc[4][0] = fma2(sp, b0, acc[4][0]); acc[4][1] = fma2(sp, b1, acc[4][1]);
            sp = splat2(a1.y); acc[5][0] = fma2(sp, b0, acc[5][0]); acc[5][1] = fma2(sp, b1, acc[5][1]);
            sp = splat2(a1.z); acc[6][0] = fma2(sp, b0, acc[6][0]); acc[6][1] = fma2(sp, b1, acc[6][1]);
            sp = splat2(a1.w); acc[7][0] = fma2(sp, b0, acc[7][0]); acc[7][1] = fma2(sp, b1, acc[7][1]);
        }
        __syncthreads();
    }
#pragma unroll
    for (int i = 0; i < 8; i++) {
        int row = bx * 128 + r0 + i;
        float bias = g_bias[row];
        float p0, p1, p2, p3;
        upk2(acc[i][0], p0, p1);
        upk2(acc[i][1], p2, p3);
        *(float4*)(g_xg + ((size_t)t * 2048 + row) * 64 + c0) =
            make_float4(p0 + bias, p1 + bias, p2 + bias, p3 + bias);
    }
}

// ---------------------------------------------------------------------------
// Phase 2: persistent recurrence, 128 CTAs x 256 threads, 1 CTA/SM.
// CTA owns 4 hidden units -> 16 gate rows (rl = unit*4 + gate).
// smem: Wt2 = pre-splatted {w,w} ull [512 k][16 rows]        = 64 KB
//       hs  = full h [512 k][64 b], TMA-filled in 4 chunks   = 128 KB
//       gp  = warp-group partials [4][16][64]                = 16 KB
// Sync (R16): producer CTA c REDs g_cnt4[c>>5] once per step. Consumer tid0
// interleaves poll(group p >= s*32) -> TMA(chunk p): chunk 0 gates on its
// 32 producers only; later groups' stragglers hide under compute phases.
// GEMM: 4 phases of 128 k gated by chunk mbars. Warp (q=wid&3) covers
// k-sub [q*32,+32) per phase, ch = wid>>2 col half.
// Lane (rg = lane>>3, cg = lane&7): 4 rows x 4 cols.
// ---------------------------------------------------------------------------
__global__ void __launch_bounds__(256, 1) k_rec(const float* __restrict__ Whh) {
    extern __shared__ __align__(16) char smraw[];
    ull*   Wt2 = (ull*)smraw;                          // 512*16 ull = 65536 B
    float* hs  = (float*)(smraw + 65536);              // 512*64 fl  = 131072 B
    float* gp  = (float*)(smraw + 65536 + 131072);     // 4*16*64 fl = 16384 B
    __shared__ __align__(8) ull mbars[4];

    const int tid  = threadIdx.x;
    const int h0   = blockIdx.x * 4;
    const int wid  = tid >> 5, lane = tid & 31;
    const int q    = wid & 3;                 // k-sub within each chunk
    const int ch   = wid >> 2;                // col half
    const int rg   = lane >> 3, cg = lane & 7;
    const int r0   = rg * 4;                  // 4 rows
    const int c0   = ch * 32 + cg * 4;        // 4 cols
    const int u2   = tid >> 6, b = tid & 63;  // cell-update mapping

    const uint32_t hs_u = s2u(hs);

    // fill pre-splatted W slab: Wt2[k*16 + rl] = {w,w},
    // w = Whh[(rl&3)*512 + h0 + (rl>>2)][k]
#pragma unroll
    for (int j = 0; j < 8; j++) {
        int flat = tid + j * 256;              // float4 idx 0..2047
        int rl = flat >> 7, k4 = flat & 127;
        int grw = (rl & 3) * 512 + h0 + (rl >> 2);
        float4 w4 = *(const float4*)(Whh + (size_t)grw * 512 + k4 * 4);
        Wt2[(k4 * 4 + 0) * 16 + rl] = splat2(w4.x);
        Wt2[(k4 * 4 + 1) * 16 + rl] = splat2(w4.y);
        Wt2[(k4 * 4 + 2) * 16 + rl] = splat2(w4.z);
        Wt2[(k4 * 4 + 3) * 16 + rl] = splat2(w4.w);
    }
    if (tid == 0) {
#pragma unroll
        for (int p = 0; p < 4; p++) mbar_init(s2u(&mbars[p]), 1u);
    }
    float cstate = 0.0f;
    __syncthreads();

    for (int s = 0; s < TSZ; s++) {
        const float* hin  = g_h + (s & 1) * 32768;
        float*       hout = g_h + ((s + 1) & 1) * 32768;
        const int    ph   = s & 1;            // mbar parity (1 use per step)

        // xg for this thread's cell (independent of h; overlaps everything)
        float xgi = __ldcs(g_xg + ((size_t)s * 2048 + 0 * 512 + h0 + u2) * 64 + b);
        float xgf = __ldcs(g_xg + ((size_t)s * 2048 + 1 * 512 + h0 + u2) * 64 + b);
        float xgg = __ldcs(g_xg + ((size_t)s * 2048 + 2 * 512 + h0 + u2) * 64 + b);
        float xgo = __ldcs(g_xg + ((size_t)s * 2048 + 3 * 512 + h0 + u2) * 64 + b);

        // ---- tid0: per-group poll -> TMA, interleaved --------------------
        if (tid == 0) {
            const unsigned target = (unsigned)s * 32u;
#pragma unroll
            for (int p = 0; p < 4; p++) {
                unsigned v;
                do {
                    asm volatile("ld.relaxed.gpu.global.u32 %0,[%1];"
                                 : "=r"(v) : "l"(&g_cnt4[p]));
                } while (v < target);
                asm volatile("fence.acq_rel.gpu;" ::: "memory");
                asm volatile("fence.proxy.async;" ::: "memory");
                uint32_t m = s2u(&mbars[p]);
                mbar_expect_tx(m, 32768u);
                bulk_g2s(hs_u + p * 32768u, hin + p * 8192, 32768u, m);
            }
        }
        // (no __syncthreads: consumers gate on the chunk mbarriers)

        // ---- GEMM: 4 phases of 128 k; warp q takes 32 k per phase --------
        ull a00 = 0, a01 = 0, a10 = 0, a11 = 0;
        ull a20 = 0, a21 = 0, a30 = 0, a31 = 0;
#pragma unroll
        for (int p = 0; p < 4; p++) {
            mbar_wait(s2u(&mbars[p]), ph);
            const int kbeg = p * 128 + q * 32;
            const ull*   wp = Wt2 + kbeg * 16;
            const float* hp = hs + kbeg * 64 + c0;
#pragma unroll
            for (int k = 0; k < 32; k++) {
                ulonglong2 wa = *(const ulonglong2*)(wp + k * 16 + r0);     // rows r0,r0+1
                ulonglong2 wb = *(const ulonglong2*)(wp + k * 16 + r0 + 2); // rows r0+2,+3
                ulonglong2 hv = *(const ulonglong2*)(hp + k * 64);          // cols c0..+3
                a00 = fma2(wa.x, hv.x, a00); a01 = fma2(wa.x, hv.y, a01);
                a10 = fma2(wa.y, hv.x, a10); a11 = fma2(wa.y, hv.y, a11);
                a20 = fma2(wb.x, hv.x, a20); a21 = fma2(wb.x, hv.y, a21);
                a30 = fma2(wb.y, hv.x, a30); a31 = fma2(wb.y, hv.y, a31);
            }
        }
        // write warp-group partials
        {
            float* gq = gp + (q * 16) * 64;
            *(ulonglong2*)(gq + (r0 + 0) * 64 + c0) = make_ulonglong2(a00, a01);
            *(ulonglong2*)(gq + (r0 + 1) * 64 + c0) = make_ulonglong2(a10, a11);
            *(ulonglong2*)(gq + (r0 + 2) * 64 + c0) = make_ulonglong2(a20, a21);
            *(ulonglong2*)(gq + (r0 + 3) * 64 + c0) = make_ulonglong2(a30, a31);
        }
        __syncthreads();

        // ---- reduce partials + cell update (one cell per thread) --------
        {
            int rI = u2 * 4 + 0, rF = u2 * 4 + 1, rG = u2 * 4 + 2, rO = u2 * 4 + 3;
            float gi = xgi, gf = xgf, gg = xgg, go = xgo;
#pragma unroll
            for (int qq = 0; qq < 4; qq++) {
                const float* gq = gp + (qq * 16) * 64;
                gi += gq[rI * 64 + b];
                gf += gq[rF * 64 + b];
                gg += gq[rG * 64 + b];
                go += gq[rO * 64 + b];
            }
            float ig = fsig(gi), fg = fsig(gf), gt = ftanh(gg), og = fsig(go);
            cstate = fg * cstate + ig * gt;
            float hv = og * ftanh(cstate);
            asm volatile("st.global.cg.f32 [%0], %1;"
                         :: "l"(hout + (h0 + u2) * 64 + b), "f"(hv) : "memory");
        }
        __syncthreads();   // all hout stores issued + all hs reads done

        // ---- publish: bump this CTA's group counter (no-return RED) -----
        if (tid == 0) {
            asm volatile("fence.acq_rel.gpu;" ::: "memory");
            asm volatile("red.relaxed.gpu.global.add.u32 [%0], %1;"
                         :: "l"(&g_cnt4[blockIdx.x >> 5]), "r"(1u) : "memory");
        }
    }
}

// ---------------------------------------------------------------------------
// FC head: out[b][o] = sum_h h_last[h][b] * W_fc[o][h] + b_fc[o]
// warp-per-output, shfl reduction. h_last = g_h buffer 0.
// ---------------------------------------------------------------------------
__global__ void __launch_bounds__(256) k_fc(const float* __restrict__ Wfc,
                                            const float* __restrict__ bfc,
                                            float* __restrict__ out) {
    int g    = blockIdx.x * 8 + (threadIdx.x >> 5);
    int lane = threadIdx.x & 31;
    int o = g >> 6, b = g & 63;
    float s = 0.0f;
#pragma unroll
    for (int j = 0; j < 16; j++) {
        int h = lane + j * 32;
        s += g_h[h * 64 + b] * Wfc[o * 512 + h];
    }
#pragma unroll
    for (int m = 16; m > 0; m >>= 1)
        s += __shfl_xor_sync(0xFFFFFFFFu, s, m);
    if (lane == 0) out[b * 10 + o] = s + bfc[o];
}

// ---------------------------------------------------------------------------
extern "C" void kernel_launch(void* const* d_in, const int* in_sizes, int n_in,
                              void* d_out, int out_size) {
    const float* x    = (const float*)d_in[0];
    const float* W_ih = (const float*)d_in[1];
    const float* W_hh = (const float*)d_in[2];
    const float* b_ih = (const float*)d_in[3];
    const float* b_hh = (const float*)d_in[4];
    const float* W_fc = (const float*)d_in[5];
    const float* b_fc = (const float*)d_in[6];
    float* out = (float*)d_out;

    const int SMEM_REC = 65536 + 131072 + 16384;   // 212992 B (<227KB cap)
    cudaFuncSetAttribute(k_rec, cudaFuncAttributeMaxDynamicSharedMemorySize, SMEM_REC);

    k_init<<<64, 256>>>(b_ih, b_hh);
    k_inproj<<<dim3(16, 2048), 256>>>(x, W_ih);
    k_rec<<<NCTA, 256, SMEM_REC>>>(W_hh);
    k_fc<<<80, 256>>>(W_fc, b_fc, out);
}

// round 17
// speedup vs baseline: 1.4754x; 1.2249x over previous
#include <cuda_runtime.h>
#include <cstdint>
#include <cstddef>
#include <math.h>

// ---------------------------------------------------------------------------
// LSTM  I=256 H=512 O=10 B=64 T=2048  (fp32, f32x2 packed-FMA pipe)
// R17: R13 (16.33ms, canonical) + cluster-4 TMA MULTICAST h staging:
//      rank r of each 4-CTA cluster loads chunk r (32KB) once and
//      multicasts it to all members' mbar[r] -> L2 broadcast traffic
//      16MB -> 4MB per step, TMA issues 512 -> 128 per step.
//      GEMM phases / tiles / counter barrier / epilogue: byte-identical R13.
// ---------------------------------------------------------------------------

#define TSZ  2048
#define NCTA 128

typedef unsigned long long ull;

// scratch (__device__ globals are the sanctioned scratch mechanism)
__device__ float    g_xg[268435456];     // 1 GiB: [T][4H][B]  (2048*2048*64)
__device__ float    g_h[2 * 512 * 64];   // double-buffered h: [H][B]
__device__ float    g_bias[2048];        // b_ih + b_hh
__device__ unsigned g_count;             // chip-barrier monotonic counter

// ---- packed f32x2 helpers (Blackwell dual-fp32 pipe) ----------------------
__device__ __forceinline__ ull splat2(float a) {
    ull r; asm("mov.b64 %0,{%1,%1};" : "=l"(r) : "f"(a)); return r;
}
__device__ __forceinline__ ull fma2(ull a, ull b, ull c) {
    ull d; asm("fma.rn.f32x2 %0,%1,%2,%3;" : "=l"(d) : "l"(a), "l"(b), "l"(c));
    return d;
}
__device__ __forceinline__ void upk2(ull v, float& a, float& b) {
    asm("mov.b64 {%0,%1},%2;" : "=f"(a), "=f"(b) : "l"(v));
}

// fast activations (rel err ~1e-6; budget 1e-3)
__device__ __forceinline__ float fsig(float x) {
    return __fdividef(1.0f, 1.0f + __expf(-x));
}
__device__ __forceinline__ float ftanh(float x) {
    return 1.0f - __fdividef(2.0f, __expf(2.0f * x) + 1.0f);
}

// ---- smem / mbarrier / bulk-copy helpers ----------------------------------
__device__ __forceinline__ uint32_t s2u(const void* p) {
    uint32_t a;
    asm("{ .reg .u64 t; cvta.to.shared.u64 t, %1; cvt.u32.u64 %0, t; }"
        : "=r"(a) : "l"(p));
    return a;
}
__device__ __forceinline__ void mbar_init(uint32_t m, unsigned cnt) {
    asm volatile("mbarrier.init.shared.b64 [%0], %1;" :: "r"(m), "r"(cnt) : "memory");
}
__device__ __forceinline__ void mbar_expect_tx(uint32_t m, unsigned bytes) {
    asm volatile("mbarrier.arrive.expect_tx.shared.b64 _, [%0], %1;"
                 :: "r"(m), "r"(bytes) : "memory");
}
__device__ __forceinline__ void mbar_wait(uint32_t m, int phase) {
    asm volatile(
        "{\n\t.reg .pred P;\n\t"
        "LW_%=:\n\t"
        "mbarrier.try_wait.parity.acquire.cta.shared::cta.b64 P, [%0], %1, 0x989680;\n\t"
        "@P bra LD_%=;\n\t"
        "bra LW_%=;\n\t"
        "LD_%=:\n\t}"
        :: "r"(m), "r"(phase) : "memory");
}
// multicast bulk copy: delivers [src,+bytes) to the same smem offset in every
// cluster CTA whose bit is set in mask; complete_tx arrives on each member's
// mbar at the same cluster-local offset.
__device__ __forceinline__ void bulk_g2s_mc(uint32_t dst, const void* src,
                                            unsigned bytes, uint32_t mbar,
                                            unsigned short mask) {
    asm volatile(
        "cp.async.bulk.shared::cluster.global.mbarrier::complete_tx::bytes"
        ".multicast::cluster [%0], [%1], %2, [%3], %4;"
        :: "r"(dst), "l"(src), "r"(bytes), "r"(mbar), "h"(mask) : "memory");
}
__device__ __forceinline__ void cluster_sync_() {
    asm volatile("barrier.cluster.arrive.aligned;" ::: "memory");
    asm volatile("barrier.cluster.wait.aligned;" ::: "memory");
}

// ---------------------------------------------------------------------------
__global__ void k_init(const float* __restrict__ bih, const float* __restrict__ bhh) {
    int tid = blockIdx.x * blockDim.x + threadIdx.x;
    int nt  = gridDim.x * blockDim.x;
    if (tid < 2048) g_bias[tid] = bih[tid] + bhh[tid];
    for (int i = tid; i < 2 * 512 * 64; i += nt) g_h[i] = 0.0f;
    if (tid == 0) g_count = 0u;
}

// ---------------------------------------------------------------------------
// Phase 1: xg[t][row][b] = sum_i W_ih[row][i] * x[b][t][i] + bias[row]
// (unchanged -- passing since R5)
// ---------------------------------------------------------------------------
__global__ void __launch_bounds__(256) k_inproj(const float* __restrict__ x,
                                                const float* __restrict__ Wih) {
    __shared__ __align__(16) float As[16 * 132];
    __shared__ __align__(16) float Bs[16 * 66];

    const int tid = threadIdx.x;
    const int bx  = blockIdx.x;
    const int t   = blockIdx.y;
    const int tr  = tid >> 4, tc = tid & 15;
    const int r0  = tr * 8,  c0 = tc * 4;
    const int kkg = tid & 3;
    const int bb  = tid >> 2;

    ull acc[8][2];
#pragma unroll
    for (int i = 0; i < 8; i++) { acc[i][0] = 0ull; acc[i][1] = 0ull; }

    for (int k0 = 0; k0 < 256; k0 += 16) {
#pragma unroll
        for (int j = 0; j < 2; j++) {
            int rr = (tid >> 2) + j * 64;
            float4 av = *(const float4*)(Wih + (size_t)(bx * 128 + rr) * 256 + k0 + kkg * 4);
            As[(kkg * 4 + 0) * 132 + rr] = av.x;
            As[(kkg * 4 + 1) * 132 + rr] = av.y;
            As[(kkg * 4 + 2) * 132 + rr] = av.z;
            As[(kkg * 4 + 3) * 132 + rr] = av.w;
        }
        {
            float4 bv = *(const float4*)(x + ((size_t)bb * 2048 + t) * 256 + k0 + kkg * 4);
            Bs[(kkg * 4 + 0) * 66 + bb] = bv.x;
            Bs[(kkg * 4 + 1) * 66 + bb] = bv.y;
            Bs[(kkg * 4 + 2) * 66 + bb] = bv.z;
            Bs[(kkg * 4 + 3) * 66 + bb] = bv.w;
        }
        __syncthreads();
#pragma unroll
        for (int k = 0; k < 16; k++) {
            float4 a0 = *(const float4*)&As[k * 132 + r0];
            float4 a1 = *(const float4*)&As[k * 132 + r0 + 4];
            ull b0 = *(const ull*)&Bs[k * 66 + c0];
            ull b1 = *(const ull*)&Bs[k * 66 + c0 + 2];
            ull sp;
            sp = splat2(a0.x); acc[0][0] = fma2(sp, b0, acc[0][0]); acc[0][1] = fma2(sp, b1, acc[0][1]);
            sp = splat2(a0.y); acc[1][0] = fma2(sp, b0, acc[1][0]); acc[1][1] = fma2(sp, b1, acc[1][1]);
            sp = splat2(a0.z); acc[2][0] = fma2(sp, b0, acc[2][0]); acc[2][1] = fma2(sp, b1, acc[2][1]);
            sp = splat2(a0.w); acc[3][0] = fma2(sp, b0, acc[3][0]); acc[3][1] = fma2(sp, b1, acc[3][1]);
            sp = splat2(a1.x); acc[4][0] = fma2(sp, b0, acc[4][0]); acc[4][1] = fma2(sp, b1, acc[4][1]);
            sp = splat2(a1.y); acc[5][0] = fma2(sp, b0, acc[5][0]); acc[5][1] = fma2(sp, b1, acc[5][1]);
            sp = splat2(a1.z); acc[6][0] = fma2(sp, b0, acc[6][0]); acc[6][1] = fma2(sp, b1, acc[6][1]);
            sp = splat2(a1.w); acc[7][0] = fma2(sp, b0, acc[7][0]); acc[7][1] = fma2(sp, b1, acc[7][1]);
        }
        __syncthreads();
    }
#pragma unroll
    for (int i = 0; i < 8; i++) {
        int row = bx * 128 + r0 + i;
        float bias = g_bias[row];
        float p0, p1, p2, p3;
        upk2(acc[i][0], p0, p1);
        upk2(acc[i][1], p2, p3);
        *(float4*)(g_xg + ((size_t)t * 2048 + row) * 64 + c0) =
            make_float4(p0 + bias, p1 + bias, p2 + bias, p3 + bias);
    }
}

// ---------------------------------------------------------------------------
// Phase 2: persistent recurrence, 128 CTAs x 256 threads, 1 CTA/SM,
// clusters of 4 (32 clusters). CTA owns 4 hidden units -> 16 gate rows.
// smem: Wt2 = pre-splatted {w,w} ull [512 k][16 rows]        = 64 KB
//       hs  = full h [512 k][64 b], MULTICAST-filled         = 128 KB
//       gp  = warp-group partials [4][16][64]                = 16 KB
// Staging (R17): after the all-CTA counter poll, tid0 expect_tx's its 4
// mbars (32KB each) and issues ONE multicast TMA of chunk `rank` (its
// cluster rank) to all 4 members -> each member's 4 chunks arrive from the
// 4 ranks. GEMM: 4 phases of 128 k gated by chunk mbars (R13-identical).
// Warp (q=wid&3) covers k-sub [q*32,+32) per phase, ch = wid>>2 col half.
// Lane (rg = lane>>3, cg = lane&7): 4 rows x 4 cols.
// ---------------------------------------------------------------------------
__global__ void __launch_bounds__(256, 1) __cluster_dims__(4, 1, 1)
k_rec(const float* __restrict__ Whh) {
    extern __shared__ __align__(16) char smraw[];
    ull*   Wt2 = (ull*)smraw;                          // 512*16 ull = 65536 B
    float* hs  = (float*)(smraw + 65536);              // 512*64 fl  = 131072 B
    float* gp  = (float*)(smraw + 65536 + 131072);     // 4*16*64 fl = 16384 B
    __shared__ __align__(8) ull mbars[4];

    const int tid  = threadIdx.x;
    const int h0   = blockIdx.x * 4;
    const int wid  = tid >> 5, lane = tid & 31;
    const int q    = wid & 3;                 // k-sub within each chunk
    const int ch   = wid >> 2;                // col half
    const int rg   = lane >> 3, cg = lane & 7;
    const int r0   = rg * 4;                  // 4 rows
    const int c0   = ch * 32 + cg * 4;        // 4 cols
    const int u2   = tid >> 6, b = tid & 63;  // cell-update mapping

    uint32_t rank;
    asm("mov.u32 %0, %%cluster_ctarank;" : "=r"(rank));
    const uint32_t hs_u = s2u(hs);

    // fill pre-splatted W slab: Wt2[k*16 + rl] = {w,w},
    // w = Whh[(rl&3)*512 + h0 + (rl>>2)][k]
#pragma unroll
    for (int j = 0; j < 8; j++) {
        int flat = tid + j * 256;              // float4 idx 0..2047
        int rl = flat >> 7, k4 = flat & 127;
        int grw = (rl & 3) * 512 + h0 + (rl >> 2);
        float4 w4 = *(const float4*)(Whh + (size_t)grw * 512 + k4 * 4);
        Wt2[(k4 * 4 + 0) * 16 + rl] = splat2(w4.x);
        Wt2[(k4 * 4 + 1) * 16 + rl] = splat2(w4.y);
        Wt2[(k4 * 4 + 2) * 16 + rl] = splat2(w4.z);
        Wt2[(k4 * 4 + 3) * 16 + rl] = splat2(w4.w);
    }
    if (tid == 0) {
#pragma unroll
        for (int p = 0; p < 4; p++) mbar_init(s2u(&mbars[p]), 1u);
        asm volatile("fence.proxy.async;" ::: "memory");
    }
    float cstate = 0.0f;
    __syncthreads();
    // all members' mbars must be initialized before any peer multicast
    cluster_sync_();

    for (int s = 0; s < TSZ; s++) {
        const float* hin  = g_h + (s & 1) * 32768;
        float*       hout = g_h + ((s + 1) & 1) * 32768;
        const int    ph   = s & 1;            // mbar parity (1 use per step)

        // xg for this thread's cell (independent of h; overlaps everything)
        float xgi = __ldcs(g_xg + ((size_t)s * 2048 + 0 * 512 + h0 + u2) * 64 + b);
        float xgf = __ldcs(g_xg + ((size_t)s * 2048 + 1 * 512 + h0 + u2) * 64 + b);
        float xgg = __ldcs(g_xg + ((size_t)s * 2048 + 2 * 512 + h0 + u2) * 64 + b);
        float xgo = __ldcs(g_xg + ((size_t)s * 2048 + 3 * 512 + h0 + u2) * 64 + b);

        // ---- tid0: wait for all CTAs (step s-1), then ONE multicast ------
        if (tid == 0) {
            const unsigned target = (unsigned)s * NCTA;
            unsigned v;
            do {
                asm volatile("ld.relaxed.gpu.global.u32 %0,[%1];"
                             : "=r"(v) : "l"(&g_count));
            } while (v < target);
            asm volatile("fence.acq_rel.gpu;" ::: "memory");
            asm volatile("fence.proxy.async;" ::: "memory");
#pragma unroll
            for (int p = 0; p < 4; p++)
                mbar_expect_tx(s2u(&mbars[p]), 32768u);
            // rank r loads chunk r once; HW replicates to all 4 members'
            // smem + mbar[r]. All-128 poll above guarantees every peer has
            // finished reading its previous hs (reads precede publish).
            bulk_g2s_mc(hs_u + rank * 32768u, hin + rank * 8192, 32768u,
                        s2u(&mbars[rank]), (unsigned short)0xF);
        }
        // (no __syncthreads: consumers gate on the chunk mbarriers)

        // ---- GEMM: 4 phases of 128 k; warp q takes 32 k per phase --------
        ull a00 = 0, a01 = 0, a10 = 0, a11 = 0;
        ull a20 = 0, a21 = 0, a30 = 0, a31 = 0;
#pragma unroll
        for (int p = 0; p < 4; p++) {
            mbar_wait(s2u(&mbars[p]), ph);
            const int kbeg = p * 128 + q * 32;
            const ull*   wp = Wt2 + kbeg * 16;
            const float* hp = hs + kbeg * 64 + c0;
#pragma unroll
            for (int k = 0; k < 32; k++) {
                ulonglong2 wa = *(const ulonglong2*)(wp + k * 16 + r0);     // rows r0,r0+1
                ulonglong2 wb = *(const ulonglong2*)(wp + k * 16 + r0 + 2); // rows r0+2,+3
                ulonglong2 hv = *(const ulonglong2*)(hp + k * 64);          // cols c0..+3
                a00 = fma2(wa.x, hv.x, a00); a01 = fma2(wa.x, hv.y, a01);
                a10 = fma2(wa.y, hv.x, a10); a11 = fma2(wa.y, hv.y, a11);
                a20 = fma2(wb.x, hv.x, a20); a21 = fma2(wb.x, hv.y, a21);
                a30 = fma2(wb.y, hv.x, a30); a31 = fma2(wb.y, hv.y, a31);
            }
        }
        // write warp-group partials
        {
            float* gq = gp + (q * 16) * 64;
            *(ulonglong2*)(gq + (r0 + 0) * 64 + c0) = make_ulonglong2(a00, a01);
            *(ulonglong2*)(gq + (r0 + 1) * 64 + c0) = make_ulonglong2(a10, a11);
            *(ulonglong2*)(gq + (r0 + 2) * 64 + c0) = make_ulonglong2(a20, a21);
            *(ulonglong2*)(gq + (r0 + 3) * 64 + c0) = make_ulonglong2(a30, a31);
        }
        __syncthreads();

        // ---- reduce partials + cell update (one cell per thread) --------
        {
            int rI = u2 * 4 + 0, rF = u2 * 4 + 1, rG = u2 * 4 + 2, rO = u2 * 4 + 3;
            float gi = xgi, gf = xgf, gg = xgg, go = xgo;
#pragma unroll
            for (int qq = 0; qq < 4; qq++) {
                const float* gq = gp + (qq * 16) * 64;
                gi += gq[rI * 64 + b];
                gf += gq[rF * 64 + b];
                gg += gq[rG * 64 + b];
                go += gq[rO * 64 + b];
            }
            float ig = fsig(gi), fg = fsig(gf), gt = ftanh(gg), og = fsig(go);
            cstate = fg * cstate + ig * gt;
            float hv = og * ftanh(cstate);
            asm volatile("st.global.cg.f32 [%0], %1;"
                         :: "l"(hout + (h0 + u2) * 64 + b), "f"(hv) : "memory");
        }
        __syncthreads();   // all hout stores issued + all hs reads done

        // ---- publish: bump global counter (no-return reduction) ---------
        if (tid == 0) {
            asm volatile("fence.acq_rel.gpu;" ::: "memory");
            asm volatile("red.relaxed.gpu.global.add.u32 [%0], %1;"
                         :: "l"(&g_count), "r"(1u) : "memory");
        }
    }
    // no CTA may exit while a peer's multicast into its smem could be live
    cluster_sync_();
}

// ---------------------------------------------------------------------------
// FC head: out[b][o] = sum_h h_last[h][b] * W_fc[o][h] + b_fc[o]
// warp-per-output, shfl reduction. h_last = g_h buffer 0.
// ---------------------------------------------------------------------------
__global__ void __launch_bounds__(256) k_fc(const float* __restrict__ Wfc,
                                            const float* __restrict__ bfc,
                                            float* __restrict__ out) {
    int g    = blockIdx.x * 8 + (threadIdx.x >> 5);
    int lane = threadIdx.x & 31;
    int o = g >> 6, b = g & 63;
    float s = 0.0f;
#pragma unroll
    for (int j = 0; j < 16; j++) {
        int h = lane + j * 32;
        s += g_h[h * 64 + b] * Wfc[o * 512 + h];
    }
#pragma unroll
    for (int m = 16; m > 0; m >>= 1)
        s += __shfl_xor_sync(0xFFFFFFFFu, s, m);
    if (lane == 0) out[b * 10 + o] = s + bfc[o];
}

// ---------------------------------------------------------------------------
extern "C" void kernel_launch(void* const* d_in, const int* in_sizes, int n_in,
                              void* d_out, int out_size) {
    const float* x    = (const float*)d_in[0];
    const float* W_ih = (const float*)d_in[1];
    const float* W_hh = (const float*)d_in[2];
    const float* b_ih = (const float*)d_in[3];
    const float* b_hh = (const float*)d_in[4];
    const float* W_fc = (const float*)d_in[5];
    const float* b_fc = (const float*)d_in[6];
    float* out = (float*)d_out;

    const int SMEM_REC = 65536 + 131072 + 16384;   // 212992 B (<227KB cap)
    cudaFuncSetAttribute(k_rec, cudaFuncAttributeMaxDynamicSharedMemorySize, SMEM_REC);

    k_init<<<64, 256>>>(b_ih, b_hh);
    k_inproj<<<dim3(16, 2048), 256>>>(x, W_ih);
    k_rec<<<NCTA, 256, SMEM_REC>>>(W_hh);
    k_fc<<<80, 256>>>(W_fc, b_fc, out);
}